// round 1
// baseline (speedup 1.0000x reference)
#include <cuda_runtime.h>
#include <math.h>
#include <stdint.h>

// ---------------------------------------------------------------------------
// Shapes (fixed by the problem)
// ---------------------------------------------------------------------------
#define LQ    1024      // sentence length
#define HIDQ  1024      // bidirectional hidden
#define HDIRQ 512       // per-direction hidden
#define DIN0  400       // WDIM + PDIM
#define MLPH  512       // MLP/2
#define G4H   2048      // 4 * HDIR

// Recurrence kernel geometry
#define NCTA_DIR 64     // CTAs per direction
#define JV       8      // h elements per CTA
#define ROWS     32     // gate rows per CTA (4 gates * JV)
#define LSTM_SMEM_BYTES ((ROWS*HDIRQ + HDIRQ + ROWS + ROWS) * 4)

// ---------------------------------------------------------------------------
// Device scratch (no allocations allowed -> __device__ globals)
// ---------------------------------------------------------------------------
__device__ float g_emb[LQ * DIN0];
__device__ float g_xp[2 * LQ * G4H];        // input projections, both dirs (16 MB)
__device__ float g_hcat0[LQ * HIDQ];        // layer-0 output (fwd cols 0:512, bwd 512:1024)
__device__ float g_hcat1[LQ * HIDQ];        // layer-1 output
__device__ float g_featH[LQ * MLPH];
__device__ float g_featM[LQ * MLPH];
__device__ float g_shead[LQ];
__device__ float g_smodif[LQ];
__device__ int   g_flags[2 * NCTA_DIR];     // per-CTA step flags

// ---------------------------------------------------------------------------
// Embedding gather: emb[l] = concat(word_emb[wt[l]], pos_emb[pt[l]])
// ---------------------------------------------------------------------------
__global__ void embed_kernel(const int* __restrict__ wt, const int* __restrict__ pt,
                             const float* __restrict__ we, const float* __restrict__ pe)
{
    int l = blockIdx.x;
    int w = wt[l];
    int p = pt[l];
    for (int k = threadIdx.x; k < DIN0; k += blockDim.x) {
        float v;
        if (k < 300) v = we[(size_t)w * 300 + k];
        else         v = pe[(size_t)p * 100 + (k - 300)];
        g_emb[(size_t)l * DIN0 + k] = v;
    }
}

// ---------------------------------------------------------------------------
// Generic SGEMM: C[m][n] = sum_k A[m][k] * W[n][k] + bias[n]
// A: [M,K] row-major, W: [N,K] row-major (i.e. C = A @ W^T + bias)
// blockIdx.z applies strides (for the 2-direction batched projections).
// ---------------------------------------------------------------------------
#define BM 64
#define BN 64
#define BK 16
__global__ void __launch_bounds__(256)
sgemm_bias_kernel(const float* __restrict__ A, const float* __restrict__ W,
                  const float* __restrict__ bias, float* __restrict__ C,
                  int M, int N, int K,
                  long long sA, long long sW, long long sB, long long sC)
{
    int z = blockIdx.z;
    A    += (size_t)z * sA;
    W    += (size_t)z * sW;
    bias += (size_t)z * sB;
    C    += (size_t)z * sC;

    int n0 = blockIdx.x * BN;
    int m0 = blockIdx.y * BM;

    __shared__ float As[BK][BM];
    __shared__ float Ws[BK][BN];

    int tid = threadIdx.x;         // 256 threads
    int lk  = tid & 15;            // k within tile
    int lm  = tid >> 4;            // row base for loads
    int tx  = tid & 15;            // micro-tile col group
    int ty  = tid >> 4;            // micro-tile row group

    float acc[4][4];
#pragma unroll
    for (int i = 0; i < 4; i++)
#pragma unroll
        for (int j = 0; j < 4; j++) acc[i][j] = 0.f;

    for (int k0 = 0; k0 < K; k0 += BK) {
        int kk = k0 + lk;
        bool kin = (kk < K);
#pragma unroll
        for (int i = 0; i < 4; i++) {
            int m = lm + i * 16;
            As[lk][m] = kin ? A[(size_t)(m0 + m) * K + kk] : 0.f;
            Ws[lk][m] = kin ? W[(size_t)(n0 + m) * K + kk] : 0.f;
        }
        __syncthreads();
#pragma unroll
        for (int k = 0; k < BK; k++) {
            float a[4], b[4];
#pragma unroll
            for (int i = 0; i < 4; i++) a[i] = As[k][ty * 4 + i];
#pragma unroll
            for (int j = 0; j < 4; j++) b[j] = Ws[k][tx * 4 + j];
#pragma unroll
            for (int i = 0; i < 4; i++)
#pragma unroll
                for (int j = 0; j < 4; j++) acc[i][j] += a[i] * b[j];
        }
        __syncthreads();
    }

#pragma unroll
    for (int i = 0; i < 4; i++) {
        int m = m0 + ty * 4 + i;
#pragma unroll
        for (int j = 0; j < 4; j++) {
            int n = n0 + tx * 4 + j;
            C[(size_t)m * N + n] = acc[i][j] + bias[n];
        }
    }
}

// ---------------------------------------------------------------------------
// Flag reset (stream-ordered before each recurrence launch; makes graph
// replays deterministic and deadlock-free)
// ---------------------------------------------------------------------------
__global__ void reset_flags_kernel()
{
    if (threadIdx.x < 2 * NCTA_DIR) g_flags[threadIdx.x] = 0;
}

// ---------------------------------------------------------------------------
// Persistent bidirectional LSTM layer.
// grid = 128 CTAs (<= SM count, all co-resident). CTA b: direction d = b/64,
// slice cb = b%64 owning h elements j in [cb*8, cb*8+8) -> 32 gate rows
// staged in SMEM once. Per step: spin on own direction's 64 flags, load full
// h (512 floats) from L2, slice mat-vec, gates, write 8 h values, release.
// ---------------------------------------------------------------------------
__global__ void __launch_bounds__(256, 1)
lstm_layer_kernel(const float* __restrict__ Whh,   // [2][2048][512]
                  const float* __restrict__ xp,    // [2][L][2048] (bias included)
                  float* __restrict__ hcat)        // [L][1024]
{
    extern __shared__ float smem[];
    float* w_s  = smem;                       // ROWS * 512
    float* h_s  = smem + ROWS * HDIRQ;        // 512
    float* g_s  = h_s + HDIRQ;                // 32
    float* xp_s = g_s + ROWS;                 // 32

    const int tid = threadIdx.x;
    const int b   = blockIdx.x;
    const int d   = b >> 6;
    const int cb  = b & 63;
    const int j0  = cb * JV;

    // Stage this CTA's Whh rows: row r = gate*8 + jl  <->  global row gate*512 + j0 + jl
    for (int r = 0; r < ROWS; r++) {
        int gate = r >> 3, jl = r & 7;
        const float* src = Whh + ((size_t)d * G4H + (size_t)gate * HDIRQ + j0 + jl) * HDIRQ;
        for (int k = tid; k < HDIRQ; k += 256) w_s[r * HDIRQ + k] = src[k];
    }
    __syncthreads();

    const int lane = tid & 31;
    const int warp = tid >> 5;
    float c_state = 0.f;                       // valid for tid < 8
    volatile int* flg = g_flags;

    for (int step = 0; step < LQ; step++) {
        const int t = (d == 0) ? step : (LQ - 1 - step);

        // Prefetch this CTA's 32 xp values for time t (issue LDG early)
        float xpv = 0.f;
        if (tid < ROWS) {
            int gate = tid >> 3, jl = tid & 7;
            xpv = xp[((size_t)d * LQ + t) * G4H + (size_t)gate * HDIRQ + j0 + jl];
        }

        if (step == 0) {
            for (int k = tid; k < HDIRQ; k += 256) h_s[k] = 0.f;
        } else {
            // Wait for all 64 CTAs of this direction to have published h_{t_prev}
            if (tid < NCTA_DIR) {
                while (flg[d * NCTA_DIR + tid] < step) { }
                __threadfence();   // acquire
            }
            __syncthreads();
            const int tp = (d == 0) ? (t - 1) : (t + 1);
            const float* hp = hcat + (size_t)tp * HIDQ + d * HDIRQ;
            for (int k = tid; k < HDIRQ; k += 256) h_s[k] = hp[k];
        }
        if (tid < ROWS) xp_s[tid] = xpv;
        __syncthreads();

        // Slice mat-vec: warp handles 4 rows; lane covers cols {q*128 + lane*4 .. +4}
        float4 hv0 = *(const float4*)&h_s[0 * 128 + lane * 4];
        float4 hv1 = *(const float4*)&h_s[1 * 128 + lane * 4];
        float4 hv2 = *(const float4*)&h_s[2 * 128 + lane * 4];
        float4 hv3 = *(const float4*)&h_s[3 * 128 + lane * 4];
#pragma unroll
        for (int rr = 0; rr < 4; rr++) {
            const int r = warp * 4 + rr;
            const float* wr = &w_s[r * HDIRQ];
            float4 w0 = *(const float4*)&wr[0 * 128 + lane * 4];
            float4 w1 = *(const float4*)&wr[1 * 128 + lane * 4];
            float4 w2 = *(const float4*)&wr[2 * 128 + lane * 4];
            float4 w3 = *(const float4*)&wr[3 * 128 + lane * 4];
            float acc = w0.x * hv0.x + w0.y * hv0.y + w0.z * hv0.z + w0.w * hv0.w;
            acc      += w1.x * hv1.x + w1.y * hv1.y + w1.z * hv1.z + w1.w * hv1.w;
            acc      += w2.x * hv2.x + w2.y * hv2.y + w2.z * hv2.z + w2.w * hv2.w;
            acc      += w3.x * hv3.x + w3.y * hv3.y + w3.z * hv3.z + w3.w * hv3.w;
#pragma unroll
            for (int o = 16; o > 0; o >>= 1)
                acc += __shfl_xor_sync(0xffffffffu, acc, o);
            if (lane == 0) g_s[r] = acc;
        }
        __syncthreads();

        // Gate combine + state update (8 owner threads, PyTorch gate order i,f,g,o)
        if (tid < JV) {
            float gi = g_s[0 * JV + tid] + xp_s[0 * JV + tid];
            float gf = g_s[1 * JV + tid] + xp_s[1 * JV + tid];
            float gg = g_s[2 * JV + tid] + xp_s[2 * JV + tid];
            float go = g_s[3 * JV + tid] + xp_s[3 * JV + tid];
            float iv = 1.f / (1.f + expf(-gi));
            float fv = 1.f / (1.f + expf(-gf));
            float gv = tanhf(gg);
            float ov = 1.f / (1.f + expf(-go));
            c_state = fv * c_state + iv * gv;
            float hv = ov * tanhf(c_state);
            hcat[(size_t)t * HIDQ + d * HDIRQ + j0 + tid] = hv;
        }
        __threadfence();       // make h writes visible gpu-wide (release part 1)
        __syncthreads();       // order all writers' fences before the flag
        if (tid == 0) flg[d * NCTA_DIR + cb] = step + 1;
    }
}

// ---------------------------------------------------------------------------
// s[l] = sum_n tanh(feat[l][n]) * wo[off + n]
// ---------------------------------------------------------------------------
__global__ void reduce_s_kernel(const float* __restrict__ feat, const float* __restrict__ wo,
                                int off, float* __restrict__ s)
{
    int l = blockIdx.x;
    int tid = threadIdx.x;
    float p = 0.f;
    for (int n = tid; n < MLPH; n += 256)
        p += tanhf(feat[(size_t)l * MLPH + n]) * wo[off + n];
    __shared__ float red[8];
#pragma unroll
    for (int o = 16; o > 0; o >>= 1) p += __shfl_xor_sync(0xffffffffu, p, o);
    if ((tid & 31) == 0) red[tid >> 5] = p;
    __syncthreads();
    if (tid < 8) {
        float v = red[tid];
#pragma unroll
        for (int o = 4; o > 0; o >>= 1) v += __shfl_xor_sync(0xffu, v, o);
        if (tid == 0) s[l] = v;
    }
}

// ---------------------------------------------------------------------------
// score[m][h] = s_modif[m] + s_head[h] + bo
// ---------------------------------------------------------------------------
__global__ void score_kernel(const float* __restrict__ sh, const float* __restrict__ sm,
                             const float* __restrict__ bo, float* __restrict__ out)
{
    int idx = blockIdx.x * 256 + threadIdx.x;
    int m = idx >> 10;
    int h = idx & 1023;
    out[idx] = sm[m] + sh[h] + bo[0];
}

// ---------------------------------------------------------------------------
// Launch sequence (graph-capturable: kernel launches only)
// ---------------------------------------------------------------------------
extern "C" void kernel_launch(void* const* d_in, const int* in_sizes, int n_in,
                              void* d_out, int out_size)
{
    (void)in_sizes; (void)n_in; (void)out_size;

    const int*   wt   = (const int*)  d_in[0];
    const int*   pt   = (const int*)  d_in[1];
    const float* we   = (const float*)d_in[2];
    const float* pe   = (const float*)d_in[3];
    const float* Wih0 = (const float*)d_in[4];
    const float* Whh0 = (const float*)d_in[5];
    const float* b0   = (const float*)d_in[6];
    const float* Wih1 = (const float*)d_in[7];
    const float* Whh1 = (const float*)d_in[8];
    const float* b1   = (const float*)d_in[9];
    const float* Wh   = (const float*)d_in[10];
    const float* bh   = (const float*)d_in[11];
    const float* Wm   = (const float*)d_in[12];
    const float* bm   = (const float*)d_in[13];
    const float* wo   = (const float*)d_in[14];
    const float* bo   = (const float*)d_in[15];
    float*       out  = (float*)d_out;

    float *p_emb, *p_xp, *p_h0, *p_h1, *p_fH, *p_fM, *p_sh, *p_sm;
    cudaGetSymbolAddress((void**)&p_emb, g_emb);
    cudaGetSymbolAddress((void**)&p_xp,  g_xp);
    cudaGetSymbolAddress((void**)&p_h0,  g_hcat0);
    cudaGetSymbolAddress((void**)&p_h1,  g_hcat1);
    cudaGetSymbolAddress((void**)&p_fH,  g_featH);
    cudaGetSymbolAddress((void**)&p_fM,  g_featM);
    cudaGetSymbolAddress((void**)&p_sh,  g_shead);
    cudaGetSymbolAddress((void**)&p_sm,  g_smodif);

    cudaFuncSetAttribute(lstm_layer_kernel,
                         cudaFuncAttributeMaxDynamicSharedMemorySize,
                         LSTM_SMEM_BYTES);

    // 1) embeddings
    embed_kernel<<<LQ, 128>>>(wt, pt, we, pe);

    // 2) layer-0 input projections: xp[d] = emb @ Wih0[d]^T + b0[d]
    {
        dim3 g(G4H / BN, LQ / BM, 2);
        sgemm_bias_kernel<<<g, 256>>>(p_emb, Wih0, b0, p_xp,
                                      LQ, G4H, DIN0,
                                      0LL, (long long)G4H * DIN0, (long long)G4H,
                                      (long long)LQ * G4H);
    }

    // 3) layer-0 recurrence
    reset_flags_kernel<<<1, 128>>>();
    lstm_layer_kernel<<<2 * NCTA_DIR, 256, LSTM_SMEM_BYTES>>>(Whh0, p_xp, p_h0);

    // 4) layer-1 input projections: xp[d] = hcat0 @ Wih1[d]^T + b1[d]
    {
        dim3 g(G4H / BN, LQ / BM, 2);
        sgemm_bias_kernel<<<g, 256>>>(p_h0, Wih1, b1, p_xp,
                                      LQ, G4H, HIDQ,
                                      0LL, (long long)G4H * HIDQ, (long long)G4H,
                                      (long long)LQ * G4H);
    }

    // 5) layer-1 recurrence
    reset_flags_kernel<<<1, 128>>>();
    lstm_layer_kernel<<<2 * NCTA_DIR, 256, LSTM_SMEM_BYTES>>>(Whh1, p_xp, p_h1);

    // 6) MLP head features
    {
        dim3 g(MLPH / BN, LQ / BM, 1);
        sgemm_bias_kernel<<<g, 256>>>(p_h1, Wh, bh, p_fH, LQ, MLPH, HIDQ, 0LL, 0LL, 0LL, 0LL);
        sgemm_bias_kernel<<<g, 256>>>(p_h1, Wm, bm, p_fM, LQ, MLPH, HIDQ, 0LL, 0LL, 0LL, 0LL);
    }

    // 7) tanh-dot reductions
    reduce_s_kernel<<<LQ, 256>>>(p_fH, wo, 0,    p_sh);
    reduce_s_kernel<<<LQ, 256>>>(p_fM, wo, MLPH, p_sm);

    // 8) broadcast score matrix
    score_kernel<<<(LQ * LQ) / 256, 256>>>(p_sh, p_sm, bo, out);
}